// round 2
// baseline (speedup 1.0000x reference)
#include <cuda_runtime.h>
#include <cuda_bf16.h>
#include <cstdint>
#include <cstddef>

#define B_    64
#define N_    1024
#define DIN_  512
#define DH_   1024

#define BM 128
#define BN 128
#define BK 32
#define SSTRIDE 48   // bf16 elems per smem row: 32 data + 16 pad (96B, 16B-multiple)

// ------------------------- static device scratch -------------------------
__device__ __nv_bfloat16 g_Xb[(size_t)B_ * N_ * DIN_];      // X bf16 [65536,512]
__device__ __nv_bfloat16 g_W1T[(size_t)DH_ * DIN_];         // W1^T bf16 [1024,512]
__device__ __nv_bfloat16 g_W2Thi[(size_t)DH_ * DH_];        // W2^T hi [1024,1024]
__device__ __nv_bfloat16 g_W2Tlo[(size_t)DH_ * DH_];        // W2^T lo
__device__ __nv_bfloat16 g_H1[(size_t)B_ * N_ * DH_];       // relu(XW1+b1) bf16
__device__ float         g_ET[(size_t)B_ * DH_ * N_];       // encoded^T [64][1024 h][1024 n]
__device__ float         g_agg[B_ * DH_];
__device__ float         g_T[B_ * DH_];
__device__ int           g_nv[B_];
__device__ int           g_kk[B_];
__device__ unsigned      g_bits[B_ * (N_ / 32)];

// ------------------------- small helpers -------------------------
__device__ __forceinline__ unsigned fkey(float f) {
    unsigned b = __float_as_uint(f);
    return (b & 0x80000000u) ? ~b : (b | 0x80000000u);
}
__device__ __forceinline__ float keyToFloat(unsigned u) {
    unsigned b = (u & 0x80000000u) ? (u ^ 0x80000000u) : ~u;
    return __uint_as_float(b);
}

__device__ __forceinline__ void mma16816(float* c, const uint32_t* a, uint32_t b0, uint32_t b1) {
    asm volatile(
        "mma.sync.aligned.m16n8k16.row.col.f32.bf16.bf16.f32 "
        "{%0,%1,%2,%3},{%4,%5,%6,%7},{%8,%9},{%0,%1,%2,%3};\n"
        : "+f"(c[0]), "+f"(c[1]), "+f"(c[2]), "+f"(c[3])
        : "r"(a[0]), "r"(a[1]), "r"(a[2]), "r"(a[3]), "r"(b0), "r"(b1));
}
__device__ __forceinline__ void ldmat4(uint32_t* r, uint32_t addr) {
    asm volatile("ldmatrix.sync.aligned.m8n8.x4.shared.b16 {%0,%1,%2,%3},[%4];\n"
                 : "=r"(r[0]), "=r"(r[1]), "=r"(r[2]), "=r"(r[3])
                 : "r"(addr));
}
#define CP16(dst, src) asm volatile("cp.async.cg.shared.global [%0],[%1],16;\n" ::"r"(dst), "l"(src))

// 32x32 bit transpose (Hacker's Delight), involution.
template <int J>
__device__ __forceinline__ void tstep(unsigned* A, unsigned m) {
#pragma unroll
    for (int k0 = 0; k0 < 16; k0++) {
        int k = ((k0 & ~(J - 1)) << 1) | (k0 & (J - 1));
        unsigned t = (A[k] ^ (A[k + J] >> J)) & m;
        A[k] ^= t;
        A[k + J] ^= (t << J);
    }
}
__device__ __forceinline__ void transpose32(unsigned* A) {
    tstep<16>(A, 0x0000FFFFu);
    tstep<8>(A, 0x00FF00FFu);
    tstep<4>(A, 0x0F0F0F0Fu);
    tstep<2>(A, 0x33333333u);
    tstep<1>(A, 0x55555555u);
}

// planes = bit-transposed keys: plane for key-bit b is planes[31-b].
// Returns key value at 0-indexed rank r over all 32*32 keys of the warp.
__device__ __forceinline__ unsigned radix_rank(const unsigned* planes, int r) {
    unsigned C = 0xFFFFFFFFu, prefix = 0u;
#pragma unroll
    for (int bit = 31; bit >= 0; --bit) {
        unsigned P = planes[31 - bit];
        unsigned zeros = C & ~P;
        int c0 = __popc(zeros);
#pragma unroll
        for (int o = 16; o; o >>= 1) c0 += __shfl_xor_sync(0xFFFFFFFFu, c0, o);
        if (r < c0) {
            C = zeros;
        } else {
            r -= c0;
            C &= P;
            prefix |= (1u << bit);
        }
    }
    return prefix;
}

// ------------------------- prep kernels -------------------------
__global__ void castX_kernel(const float* __restrict__ X) {
    size_t i = (size_t)blockIdx.x * blockDim.x + threadIdx.x;  // float4 index
    float4 v = ((const float4*)X)[i];
    __nv_bfloat162* p = (__nv_bfloat162*)&g_Xb[4 * i];
    p[0] = __floats2bfloat162_rn(v.x, v.y);
    p[1] = __floats2bfloat162_rn(v.z, v.w);
}

// W1 [512 k][1024 n] f32 -> g_W1T [1024 n][512 k] bf16
__global__ void transW1_kernel(const float* __restrict__ W) {
    __shared__ float tile[32][33];
    int tx = threadIdx.x, ty = threadIdx.y;
    int x = blockIdx.x * 32 + tx;  // n
#pragma unroll
    for (int i = 0; i < 32; i += 8) {
        int y = blockIdx.y * 32 + ty + i;  // k
        tile[ty + i][tx] = W[(size_t)y * DH_ + x];
    }
    __syncthreads();
    int xo = blockIdx.y * 32 + tx;  // k
#pragma unroll
    for (int i = 0; i < 32; i += 8) {
        int yo = blockIdx.x * 32 + ty + i;  // n
        g_W1T[(size_t)yo * DIN_ + xo] = __float2bfloat16(tile[tx][ty + i]);
    }
}

// W2 [1024 k][1024 n] f32 -> g_W2Thi/lo [n][k]
__global__ void transW2_kernel(const float* __restrict__ W) {
    __shared__ float tile[32][33];
    int tx = threadIdx.x, ty = threadIdx.y;
    int x = blockIdx.x * 32 + tx;  // n
#pragma unroll
    for (int i = 0; i < 32; i += 8) {
        int y = blockIdx.y * 32 + ty + i;  // k
        tile[ty + i][tx] = W[(size_t)y * DH_ + x];
    }
    __syncthreads();
    int xo = blockIdx.y * 32 + tx;  // k
#pragma unroll
    for (int i = 0; i < 32; i += 8) {
        int yo = blockIdx.x * 32 + ty + i;  // n
        float w = tile[tx][ty + i];
        __nv_bfloat16 hi = __float2bfloat16(w);
        float lo = w - __bfloat162float(hi);
        g_W2Thi[(size_t)yo * DH_ + xo] = hi;
        g_W2Tlo[(size_t)yo * DH_ + xo] = __float2bfloat16(lo);
    }
}

__global__ void nvbits_kernel(const float* __restrict__ mask) {
    int b = blockIdx.x, t = threadIdx.x;
    int v = mask[(size_t)b * N_ + t] > 0.0f;
    unsigned word = __ballot_sync(0xFFFFFFFFu, v);
    __shared__ int cnt;
    if (t == 0) cnt = 0;
    __syncthreads();
    if ((t & 31) == 0) {
        g_bits[b * 32 + (t >> 5)] = word;
        atomicAdd(&cnt, __popc(word));
    }
    __syncthreads();
    if (t == 0) {
        g_nv[b] = cnt;
        g_kk[b] = (int)((float)cnt * 0.1f);
    }
}

// ------------------------- main GEMM -------------------------
// A [M,K] row-major bf16; B0/B1 [N,K] row-major ("col-major" operand) bf16.
// FUSE=true : outB = relu(A@B0^T + bias) as bf16 [M,N]
// FUSE=false: outT[b][col][n] = (A@(B0+B1)^T + bias), b=row>>10, n=row&1023
template <int NSPLIT, bool FUSE>
__global__ void __launch_bounds__(256) gemm_kernel(
    const __nv_bfloat16* __restrict__ A, const __nv_bfloat16* __restrict__ B0,
    const __nv_bfloat16* __restrict__ B1, const float* __restrict__ bias,
    __nv_bfloat16* __restrict__ outB, float* __restrict__ outT,
    int M, int N, int K) {
    extern __shared__ __nv_bfloat16 sm[];
    const int stageElems = (1 + NSPLIT) * BM * SSTRIDE;

    int tid = threadIdx.x;
    int lane = tid & 31;
    int wid = tid >> 5;
    int wm = (wid >> 2) * 64;
    int wn = (wid & 3) * 32;
    int gq = lane >> 2, tg = lane & 3;
    int mBase = blockIdx.y * BM, nBase = blockIdx.x * BN;
    int KT = K / BK;

    float acc[4][4][4];
#pragma unroll
    for (int a = 0; a < 4; a++)
#pragma unroll
        for (int b = 0; b < 4; b++)
#pragma unroll
            for (int c = 0; c < 4; c++) acc[a][b][c] = 0.f;

    auto load = [&](int kt, int s) {
        __nv_bfloat16* sa = sm + s * stageElems;
        int k0 = kt * BK;
#pragma unroll
        for (int p = 0; p < 2; p++) {
            int v = tid + 256 * p;
            int row = v >> 2;
            int cv = (v & 3) * 8;
            uint32_t dA = (uint32_t)__cvta_generic_to_shared(sa + row * SSTRIDE + cv);
            CP16(dA, A + (size_t)(mBase + row) * K + k0 + cv);
            uint32_t dB0 = (uint32_t)__cvta_generic_to_shared(sa + BM * SSTRIDE + row * SSTRIDE + cv);
            CP16(dB0, B0 + (size_t)(nBase + row) * K + k0 + cv);
            if (NSPLIT == 2) {
                uint32_t dB1 = (uint32_t)__cvta_generic_to_shared(sa + 2 * BM * SSTRIDE + row * SSTRIDE + cv);
                CP16(dB1, B1 + (size_t)(nBase + row) * K + k0 + cv);
            }
        }
        asm volatile("cp.async.commit_group;\n");
    };

    load(0, 0);
    for (int kt = 0; kt < KT; kt++) {
        asm volatile("cp.async.wait_group 0;\n");
        __syncthreads();
        if (kt + 1 < KT) load(kt + 1, (kt + 1) & 1);

        const __nv_bfloat16* sa = sm + (kt & 1) * stageElems;
        const __nv_bfloat16* sb0 = sa + BM * SSTRIDE;
        const __nv_bfloat16* sb1 = sb0 + BM * SSTRIDE;
#pragma unroll
        for (int kk = 0; kk < BK; kk += 16) {
            uint32_t af[4][4];
#pragma unroll
            for (int mi = 0; mi < 4; mi++) {
                uint32_t ad = (uint32_t)__cvta_generic_to_shared(
                    sa + (wm + mi * 16 + (lane & 15)) * SSTRIDE + kk + (lane >> 4) * 8);
                ldmat4(af[mi], ad);
            }
#pragma unroll
            for (int ni = 0; ni < 4; ni++) {
                const __nv_bfloat16* bp = sb0 + (wn + ni * 8 + gq) * SSTRIDE + kk + 2 * tg;
                uint32_t b0 = *(const uint32_t*)bp;
                uint32_t b1v = *(const uint32_t*)(bp + 8);
#pragma unroll
                for (int mi = 0; mi < 4; mi++) mma16816(acc[mi][ni], af[mi], b0, b1v);
                if (NSPLIT == 2) {
                    const __nv_bfloat16* bq = sb1 + (wn + ni * 8 + gq) * SSTRIDE + kk + 2 * tg;
                    uint32_t c0 = *(const uint32_t*)bq;
                    uint32_t c1v = *(const uint32_t*)(bq + 8);
#pragma unroll
                    for (int mi = 0; mi < 4; mi++) mma16816(acc[mi][ni], af[mi], c0, c1v);
                }
            }
        }
    }

#pragma unroll
    for (int mi = 0; mi < 4; mi++)
#pragma unroll
        for (int ni = 0; ni < 4; ni++) {
            int col = nBase + wn + ni * 8 + 2 * tg;
            int r0 = mBase + wm + mi * 16 + gq;
            float bv0 = bias[col], bv1 = bias[col + 1];
            float v00 = acc[mi][ni][0] + bv0, v01 = acc[mi][ni][1] + bv1;
            float v10 = acc[mi][ni][2] + bv0, v11 = acc[mi][ni][3] + bv1;
            if (FUSE) {
                v00 = fmaxf(v00, 0.f); v01 = fmaxf(v01, 0.f);
                v10 = fmaxf(v10, 0.f); v11 = fmaxf(v11, 0.f);
                *(__nv_bfloat162*)(outB + (size_t)r0 * N + col) = __floats2bfloat162_rn(v00, v01);
                *(__nv_bfloat162*)(outB + (size_t)(r0 + 8) * N + col) = __floats2bfloat162_rn(v10, v11);
            } else {
                int bb = r0 >> 10, nn = r0 & 1023;
                size_t base = ((size_t)bb << 20) + ((size_t)col << 10) + nn;
                outT[base] = v00;
                outT[base + 1024] = v01;
                outT[base + 8] = v10;
                outT[base + 1024 + 8] = v11;
            }
        }
}

// ------------------------- trimmed-mean select (1 warp per column) ------
__global__ void __launch_bounds__(256) select_kernel() {
    int warp = (blockIdx.x << 3) + (threadIdx.x >> 5);  // = b*1024 + h
    int lane = threadIdx.x & 31;
    int b = warp >> 10;
    const float* col = g_ET + ((size_t)warp << 10);

    unsigned keys[32];
#pragma unroll
    for (int j = 0; j < 8; j++) {
        int n0 = j * 128 + lane * 4;
        float4 v = *(const float4*)(col + n0);
        unsigned wbits = g_bits[(b << 5) + (n0 >> 5)];
        float xv[4] = {v.x, v.y, v.z, v.w};
#pragma unroll
        for (int i = 0; i < 4; i++) {
            unsigned bit = (wbits >> ((n0 + i) & 31)) & 1u;
            keys[4 * j + i] = bit ? fkey(xv[i]) : 0xFFFFFFFFu;
        }
    }

    int nv = g_nv[b], kT = g_kk[b];

    transpose32(keys);  // -> bit planes
    unsigned T2 = radix_rank(keys, nv - kT - 1);
    unsigned T1 = 0;
    if (kT > 0) T1 = radix_rank(keys, kT - 1);
    transpose32(keys);  // back to keys

    int c1 = 0, c2 = 0;
    float s1 = 0.f, s2 = 0.f;
#pragma unroll
    for (int i = 0; i < 32; i++) {
        unsigned kv = keys[i];
        float fv = keyToFloat(kv);
        if (kT > 0 && kv < T1) { c1++; s1 += fv; }
        if (kv < T2) { c2++; s2 += fv; }
    }
#pragma unroll
    for (int o = 16; o; o >>= 1) {
        c1 += __shfl_xor_sync(0xFFFFFFFFu, c1, o);
        c2 += __shfl_xor_sync(0xFFFFFFFFu, c2, o);
        s1 += __shfl_xor_sync(0xFFFFFFFFu, s1, o);
        s2 += __shfl_xor_sync(0xFFFFFFFFu, s2, o);
    }
    float Sk = (kT > 0) ? (s1 + (float)(kT - c1) * keyToFloat(T1)) : 0.f;
    float Snk = s2 + (float)((nv - kT) - c2) * keyToFloat(T2);
    if (lane == 0) g_agg[warp] = (Snk - Sk) / (float)(nv - 2 * kT);
}

// ------------------------- decode MLP -------------------------
__global__ void decode1_kernel(const float* __restrict__ W3, const float* __restrict__ b3) {
    __shared__ float sa[8][1024];
    int h = blockIdx.x * 128 + threadIdx.x;
    int bg = blockIdx.y * 8;
    for (int i = threadIdx.x; i < 8 * 1024; i += 128)
        sa[i >> 10][i & 1023] = g_agg[(bg + (i >> 10)) * 1024 + (i & 1023)];
    __syncthreads();
    float accv[8];
#pragma unroll
    for (int ii = 0; ii < 8; ii++) accv[ii] = 0.f;
    for (int k2 = 0; k2 < 1024; k2++) {
        float w = W3[(size_t)k2 * 1024 + h];
#pragma unroll
        for (int ii = 0; ii < 8; ii++) accv[ii] += sa[ii][k2] * w;
    }
    float bb = b3[h];
#pragma unroll
    for (int ii = 0; ii < 8; ii++) g_T[(bg + ii) * 1024 + h] = fmaxf(accv[ii] + bb, 0.f);
}

__global__ void decode2_kernel(const float* __restrict__ W4, const float* __restrict__ b4,
                               float* __restrict__ out) {
    int gw = blockIdx.x * 8 + (threadIdx.x >> 5);
    int lane = threadIdx.x & 31;
    if (gw >= 640) return;
    int b = gw / 10, o = gw - 10 * b;
    float acc = 0.f;
#pragma unroll
    for (int i = 0; i < 32; i++) {
        int kidx = i * 32 + lane;
        acc += g_T[b * 1024 + kidx] * W4[(size_t)kidx * 10 + o];
    }
#pragma unroll
    for (int oo = 16; oo; oo >>= 1) acc += __shfl_xor_sync(0xFFFFFFFFu, acc, oo);
    if (lane == 0) out[b * 10 + o] = acc + b4[o];
}

// ------------------------- launch -------------------------
extern "C" void kernel_launch(void* const* d_in, const int* in_sizes, int n_in,
                              void* d_out, int out_size) {
    const float* X = (const float*)d_in[0];
    const float* mask = (const float*)d_in[1];
    const float* W1 = (const float*)d_in[2];
    const float* b1 = (const float*)d_in[3];
    const float* W2 = (const float*)d_in[4];
    const float* b2 = (const float*)d_in[5];
    const float* W3 = (const float*)d_in[6];
    const float* b3 = (const float*)d_in[7];
    const float* W4 = (const float*)d_in[8];
    const float* b4 = (const float*)d_in[9];
    float* out = (float*)d_out;

    void *pXb, *pW1T, *pW2hi, *pW2lo, *pH1, *pET;
    cudaGetSymbolAddress(&pXb, g_Xb);
    cudaGetSymbolAddress(&pW1T, g_W1T);
    cudaGetSymbolAddress(&pW2hi, g_W2Thi);
    cudaGetSymbolAddress(&pW2lo, g_W2Tlo);
    cudaGetSymbolAddress(&pH1, g_H1);
    cudaGetSymbolAddress(&pET, g_ET);

    cudaFuncSetAttribute(gemm_kernel<1, true>, cudaFuncAttributeMaxDynamicSharedMemorySize, 49152);
    cudaFuncSetAttribute(gemm_kernel<2, false>, cudaFuncAttributeMaxDynamicSharedMemorySize, 73728);

    castX_kernel<<<32768, 256>>>(X);
    transW1_kernel<<<dim3(32, 16), dim3(32, 8)>>>(W1);
    transW2_kernel<<<dim3(32, 32), dim3(32, 8)>>>(W2);
    nvbits_kernel<<<64, 1024>>>(mask);

    gemm_kernel<1, true><<<dim3(DH_ / BN, (B_ * N_) / BM), 256, 49152>>>(
        (const __nv_bfloat16*)pXb, (const __nv_bfloat16*)pW1T, (const __nv_bfloat16*)pW1T,
        b1, (__nv_bfloat16*)pH1, nullptr, B_ * N_, DH_, DIN_);

    gemm_kernel<2, false><<<dim3(DH_ / BN, (B_ * N_) / BM), 256, 73728>>>(
        (const __nv_bfloat16*)pH1, (const __nv_bfloat16*)pW2hi, (const __nv_bfloat16*)pW2lo,
        b2, nullptr, (float*)pET, B_ * N_, DH_, DH_);

    select_kernel<<<(B_ * DH_) / 8, 256>>>();
    decode1_kernel<<<dim3(8, 8), 128>>>(W3, b3);
    decode2_kernel<<<80, 256>>>(W4, b4, out);
}

// round 3
// speedup vs baseline: 1.3675x; 1.3675x over previous
#include <cuda_runtime.h>
#include <cuda_fp16.h>
#include <cstdint>
#include <cstddef>

#define B_    64
#define N_    1024
#define DIN_  512
#define DH_   1024

#define BM 128
#define BN 128
#define BK 32
#define SSTRIDE 40   // fp16 elems per smem row: 32 data + 8 pad (80B, 16B-multiple, LDSM conflict-free)

// ------------------------- static device scratch -------------------------
__device__ __half g_Xh[(size_t)B_ * N_ * DIN_];       // X fp16 [65536,512]
__device__ __half g_W1T[(size_t)DH_ * DIN_];          // W1^T fp16 [1024,512]
__device__ __half g_W2T[(size_t)DH_ * DH_];           // W2^T fp16 [1024,1024]
__device__ __half g_H1[(size_t)B_ * N_ * DH_];        // relu(XW1+b1) fp16 [65536,1024]
__device__ __half g_ET[(size_t)B_ * DH_ * N_];        // encoded^T fp16 [64][1024 h][1024 n]
__device__ float  g_agg[B_ * DH_];
__device__ float  g_T[B_ * DH_];
__device__ int    g_nv[B_];
__device__ int    g_kk[B_];
__device__ unsigned g_bits[B_ * (N_ / 32)];

// ------------------------- helpers -------------------------
__device__ __forceinline__ float keyToFloat16(unsigned k32) {
    unsigned t = k32 >> 16;
    unsigned short b = (t & 0x8000u) ? (unsigned short)(t ^ 0x8000u) : (unsigned short)(~t & 0xFFFFu);
    return __half2float(__ushort_as_half(b));
}

__device__ __forceinline__ void mma16816(float* c, const uint32_t* a, uint32_t b0, uint32_t b1) {
    asm volatile(
        "mma.sync.aligned.m16n8k16.row.col.f32.f16.f16.f32 "
        "{%0,%1,%2,%3},{%4,%5,%6,%7},{%8,%9},{%0,%1,%2,%3};\n"
        : "+f"(c[0]), "+f"(c[1]), "+f"(c[2]), "+f"(c[3])
        : "r"(a[0]), "r"(a[1]), "r"(a[2]), "r"(a[3]), "r"(b0), "r"(b1));
}
__device__ __forceinline__ void ldmat4(uint32_t* r, uint32_t addr) {
    asm volatile("ldmatrix.sync.aligned.m8n8.x4.shared.b16 {%0,%1,%2,%3},[%4];\n"
                 : "=r"(r[0]), "=r"(r[1]), "=r"(r[2]), "=r"(r[3])
                 : "r"(addr));
}
#define CP16(dst, src) asm volatile("cp.async.cg.shared.global [%0],[%1],16;\n" ::"r"(dst), "l"(src))

// 32x32 bit transpose (Hacker's Delight), involution.
template <int J>
__device__ __forceinline__ void tstep(unsigned* A, unsigned m) {
#pragma unroll
    for (int k0 = 0; k0 < 16; k0++) {
        int k = ((k0 & ~(J - 1)) << 1) | (k0 & (J - 1));
        unsigned t = (A[k] ^ (A[k + J] >> J)) & m;
        A[k] ^= t;
        A[k + J] ^= (t << J);
    }
}
__device__ __forceinline__ void transpose32(unsigned* A) {
    tstep<16>(A, 0x0000FFFFu);
    tstep<8>(A, 0x00FF00FFu);
    tstep<4>(A, 0x0F0F0F0Fu);
    tstep<2>(A, 0x33333333u);
    tstep<1>(A, 0x55555555u);
}

// planes = bit-transposed keys (keys live in bits 31..16). Rank r over warp's 1024 keys.
__device__ __forceinline__ unsigned radix_rank16(const unsigned* planes, int r) {
    unsigned C = 0xFFFFFFFFu, prefix = 0u;
#pragma unroll
    for (int bit = 31; bit >= 16; --bit) {
        unsigned P = planes[31 - bit];
        unsigned zeros = C & ~P;
        int c0 = __popc(zeros);
#pragma unroll
        for (int o = 16; o; o >>= 1) c0 += __shfl_xor_sync(0xFFFFFFFFu, c0, o);
        if (r < c0) {
            C = zeros;
        } else {
            r -= c0;
            C &= P;
            prefix |= (1u << bit);
        }
    }
    return prefix;
}

// ------------------------- prep kernels -------------------------
__global__ void castX_kernel(const float* __restrict__ X) {
    size_t i = (size_t)blockIdx.x * blockDim.x + threadIdx.x;  // float4 index
    float4 v = ((const float4*)X)[i];
    __half2* p = (__half2*)&g_Xh[4 * i];
    p[0] = __floats2half2_rn(v.x, v.y);
    p[1] = __floats2half2_rn(v.z, v.w);
}

// W [Krows,1024] f32 -> WT [1024,Krows] fp16
__global__ void transW_kernel(const float* __restrict__ W, __half* __restrict__ WT, int Krows) {
    __shared__ float tile[32][33];
    int tx = threadIdx.x, ty = threadIdx.y;
    int x = blockIdx.x * 32 + tx;  // n
#pragma unroll
    for (int i = 0; i < 32; i += 8) {
        int y = blockIdx.y * 32 + ty + i;  // k
        tile[ty + i][tx] = W[(size_t)y * DH_ + x];
    }
    __syncthreads();
    int xo = blockIdx.y * 32 + tx;  // k
#pragma unroll
    for (int i = 0; i < 32; i += 8) {
        int yo = blockIdx.x * 32 + ty + i;  // n
        WT[(size_t)yo * Krows + xo] = __float2half_rn(tile[tx][ty + i]);
    }
}

__global__ void nvbits_kernel(const float* __restrict__ mask) {
    int b = blockIdx.x, t = threadIdx.x;
    int v = mask[(size_t)b * N_ + t] > 0.0f;
    unsigned word = __ballot_sync(0xFFFFFFFFu, v);
    __shared__ int cnt;
    if (t == 0) cnt = 0;
    __syncthreads();
    if ((t & 31) == 0) {
        g_bits[b * 32 + (t >> 5)] = word;
        atomicAdd(&cnt, __popc(word));
    }
    __syncthreads();
    if (t == 0) {
        g_nv[b] = cnt;
        g_kk[b] = (int)((float)cnt * 0.1f);
    }
}

// ------------------------- main GEMM (fp16 in, fp16 out, fp32 accum) -----
// A [.., K] row-major; B [.., K] row-major (col-major MMA operand).
// out[r, c] (row stride N) = A[r,:]·B[c,:] + bias; RELU optional.
// BIAS_BY_ROW: bias indexed by output row (GEMM2: b2[h]); else by column.
// blockIdx.z strides: A += z*zA, B += z*zB, out += z*zC.
template <bool RELU, bool BIAS_BY_ROW>
__global__ void __launch_bounds__(256) gemm_fp16(
    const __half* __restrict__ A, const __half* __restrict__ B,
    const float* __restrict__ bias, __half* __restrict__ out,
    int K, int N, size_t zA, size_t zB, size_t zC) {
    __shared__ __half sm[2 * 2 * BM * SSTRIDE];
    const int stageElems = 2 * BM * SSTRIDE;

    A += (size_t)blockIdx.z * zA;
    B += (size_t)blockIdx.z * zB;
    out += (size_t)blockIdx.z * zC;

    int tid = threadIdx.x;
    int lane = tid & 31;
    int wid = tid >> 5;
    int wm = (wid >> 2) * 64;
    int wn = (wid & 3) * 32;
    int gq = lane >> 2, tg = lane & 3;
    int mBase = blockIdx.y * BM, nBase = blockIdx.x * BN;
    int KT = K / BK;

    float acc[4][4][4];
#pragma unroll
    for (int a = 0; a < 4; a++)
#pragma unroll
        for (int b = 0; b < 4; b++)
#pragma unroll
            for (int c = 0; c < 4; c++) acc[a][b][c] = 0.f;

    auto load = [&](int kt, int s) {
        __half* sa = sm + s * stageElems;
        int k0 = kt * BK;
#pragma unroll
        for (int p = 0; p < 2; p++) {
            int v = tid + 256 * p;
            int row = v >> 2;
            int cv = (v & 3) * 8;
            uint32_t dA = (uint32_t)__cvta_generic_to_shared(sa + row * SSTRIDE + cv);
            CP16(dA, A + (size_t)(mBase + row) * K + k0 + cv);
            uint32_t dB = (uint32_t)__cvta_generic_to_shared(sa + BM * SSTRIDE + row * SSTRIDE + cv);
            CP16(dB, B + (size_t)(nBase + row) * K + k0 + cv);
        }
        asm volatile("cp.async.commit_group;\n");
    };

    load(0, 0);
    for (int kt = 0; kt < KT; kt++) {
        asm volatile("cp.async.wait_group 0;\n");
        __syncthreads();
        if (kt + 1 < KT) load(kt + 1, (kt + 1) & 1);

        const __half* sa = sm + (kt & 1) * stageElems;
        const __half* sb = sa + BM * SSTRIDE;
#pragma unroll
        for (int kk = 0; kk < BK; kk += 16) {
            uint32_t af[4][4];
#pragma unroll
            for (int mi = 0; mi < 4; mi++) {
                uint32_t ad = (uint32_t)__cvta_generic_to_shared(
                    sa + (wm + mi * 16 + (lane & 15)) * SSTRIDE + kk + (lane >> 4) * 8);
                ldmat4(af[mi], ad);
            }
#pragma unroll
            for (int ni = 0; ni < 4; ni++) {
                const __half* bp = sb + (wn + ni * 8 + gq) * SSTRIDE + kk + 2 * tg;
                uint32_t b0 = *(const uint32_t*)bp;
                uint32_t b1v = *(const uint32_t*)(bp + 8);
#pragma unroll
                for (int mi = 0; mi < 4; mi++) mma16816(acc[mi][ni], af[mi], b0, b1v);
            }
        }
    }

#pragma unroll
    for (int mi = 0; mi < 4; mi++) {
        int r0 = mBase + wm + mi * 16 + gq;
        float bvR0 = 0.f, bvR1 = 0.f;
        if (BIAS_BY_ROW) { bvR0 = bias[r0]; bvR1 = bias[r0 + 8]; }
#pragma unroll
        for (int ni = 0; ni < 4; ni++) {
            int col = nBase + wn + ni * 8 + 2 * tg;
            float v00, v01, v10, v11;
            if (BIAS_BY_ROW) {
                v00 = acc[mi][ni][0] + bvR0; v01 = acc[mi][ni][1] + bvR0;
                v10 = acc[mi][ni][2] + bvR1; v11 = acc[mi][ni][3] + bvR1;
            } else {
                float bv0 = bias[col], bv1 = bias[col + 1];
                v00 = acc[mi][ni][0] + bv0; v01 = acc[mi][ni][1] + bv1;
                v10 = acc[mi][ni][2] + bv0; v11 = acc[mi][ni][3] + bv1;
            }
            if (RELU) {
                v00 = fmaxf(v00, 0.f); v01 = fmaxf(v01, 0.f);
                v10 = fmaxf(v10, 0.f); v11 = fmaxf(v11, 0.f);
            }
            *(__half2*)(out + (size_t)r0 * N + col) = __floats2half2_rn(v00, v01);
            *(__half2*)(out + (size_t)(r0 + 8) * N + col) = __floats2half2_rn(v10, v11);
        }
    }
}

// ------------------------- trimmed-mean select (1 warp per column) ------
// sum(ranks kT..nv-kT-1) = S(nv-kT smallest) - S(kT smallest), exact ties via
// (m - count_lt)*threshold_value. Keys are fp16 order-preserving 16-bit maps.
__global__ void __launch_bounds__(256) select_kernel() {
    int warp = (blockIdx.x << 3) + (threadIdx.x >> 5);  // = b*1024 + h
    int lane = threadIdx.x & 31;
    int b = warp >> 10;
    const __half* col = g_ET + ((size_t)warp << 10);

    unsigned keys[32];
#pragma unroll
    for (int j = 0; j < 4; j++) {
        int n0 = j * 256 + lane * 8;
        uint4 v = *(const uint4*)(col + n0);
        unsigned wbits = g_bits[(b << 5) + (n0 >> 5)];
        unsigned ws[4] = {v.x, v.y, v.z, v.w};
#pragma unroll
        for (int i = 0; i < 8; i++) {
            unsigned h = (ws[i >> 1] >> ((i & 1) * 16)) & 0xFFFFu;
            unsigned k16 = (h & 0x8000u) ? (~h & 0xFFFFu) : (h | 0x8000u);
            unsigned bit = (wbits >> ((n0 + i) & 31)) & 1u;
            keys[j * 8 + i] = bit ? (k16 << 16) : 0xFFFF0000u;
        }
    }

    int nv = g_nv[b], kT = g_kk[b];

    transpose32(keys);  // -> bit planes (planes[0..15] = key bits 31..16)
    unsigned T2 = radix_rank16(keys, nv - kT - 1);
    unsigned T1 = 0;
    if (kT > 0) T1 = radix_rank16(keys, kT - 1);
    transpose32(keys);  // involution: back to keys

    int c1 = 0, c2 = 0;
    float s1 = 0.f, s2 = 0.f;
#pragma unroll
    for (int i = 0; i < 32; i++) {
        unsigned kv = keys[i];
        float fv = keyToFloat16(kv);
        if (kT > 0 && kv < T1) { c1++; s1 += fv; }
        if (kv < T2) { c2++; s2 += fv; }
    }
#pragma unroll
    for (int o = 16; o; o >>= 1) {
        c1 += __shfl_xor_sync(0xFFFFFFFFu, c1, o);
        c2 += __shfl_xor_sync(0xFFFFFFFFu, c2, o);
        s1 += __shfl_xor_sync(0xFFFFFFFFu, s1, o);
        s2 += __shfl_xor_sync(0xFFFFFFFFu, s2, o);
    }
    float Sk = (kT > 0) ? (s1 + (float)(kT - c1) * keyToFloat16(T1)) : 0.f;
    float Snk = s2 + (float)((nv - kT) - c2) * keyToFloat16(T2);
    if (lane == 0) g_agg[warp] = (Snk - Sk) / (float)(nv - 2 * kT);
}

// ------------------------- decode MLP -------------------------
__global__ void decode1_kernel(const float* __restrict__ W3, const float* __restrict__ b3) {
    __shared__ float sa[8][1024];
    int h = blockIdx.x * 128 + threadIdx.x;
    int bg = blockIdx.y * 8;
    for (int i = threadIdx.x; i < 8 * 1024; i += 128)
        sa[i >> 10][i & 1023] = g_agg[(bg + (i >> 10)) * 1024 + (i & 1023)];
    __syncthreads();
    float accv[8];
#pragma unroll
    for (int ii = 0; ii < 8; ii++) accv[ii] = 0.f;
    for (int k2 = 0; k2 < 1024; k2++) {
        float w = W3[(size_t)k2 * 1024 + h];
#pragma unroll
        for (int ii = 0; ii < 8; ii++) accv[ii] += sa[ii][k2] * w;
    }
    float bb = b3[h];
#pragma unroll
    for (int ii = 0; ii < 8; ii++) g_T[(bg + ii) * 1024 + h] = fmaxf(accv[ii] + bb, 0.f);
}

__global__ void decode2_kernel(const float* __restrict__ W4, const float* __restrict__ b4,
                               float* __restrict__ out) {
    int gw = blockIdx.x * 8 + (threadIdx.x >> 5);
    int lane = threadIdx.x & 31;
    if (gw >= 640) return;
    int b = gw / 10, o = gw - 10 * b;
    float acc = 0.f;
#pragma unroll
    for (int i = 0; i < 32; i++) {
        int kidx = i * 32 + lane;
        acc += g_T[b * 1024 + kidx] * W4[(size_t)kidx * 10 + o];
    }
#pragma unroll
    for (int oo = 16; oo; oo >>= 1) acc += __shfl_xor_sync(0xFFFFFFFFu, acc, oo);
    if (lane == 0) out[b * 10 + o] = acc + b4[o];
}

// ------------------------- launch -------------------------
extern "C" void kernel_launch(void* const* d_in, const int* in_sizes, int n_in,
                              void* d_out, int out_size) {
    const float* X = (const float*)d_in[0];
    const float* mask = (const float*)d_in[1];
    const float* W1 = (const float*)d_in[2];
    const float* b1 = (const float*)d_in[3];
    const float* W2 = (const float*)d_in[4];
    const float* b2 = (const float*)d_in[5];
    const float* W3 = (const float*)d_in[6];
    const float* b3 = (const float*)d_in[7];
    const float* W4 = (const float*)d_in[8];
    const float* b4 = (const float*)d_in[9];
    float* out = (float*)d_out;

    void *pXh, *pW1T, *pW2T, *pH1, *pET;
    cudaGetSymbolAddress(&pXh, g_Xh);
    cudaGetSymbolAddress(&pW1T, g_W1T);
    cudaGetSymbolAddress(&pW2T, g_W2T);
    cudaGetSymbolAddress(&pH1, g_H1);
    cudaGetSymbolAddress(&pET, g_ET);

    castX_kernel<<<32768, 256>>>(X);
    transW_kernel<<<dim3(32, 16), dim3(32, 8)>>>(W1, (__half*)pW1T, DIN_);
    transW_kernel<<<dim3(32, 32), dim3(32, 8)>>>(W2, (__half*)pW2T, DH_);
    nvbits_kernel<<<64, 1024>>>(mask);

    // GEMM1: H1[m, h] = relu(X[m,:]·W1T[h,:] + b1[h]),  m over 65536
    gemm_fp16<true, false><<<dim3(DH_ / BN, (B_ * N_) / BM, 1), 256>>>(
        (const __half*)pXh, (const __half*)pW1T, b1, (__half*)pH1,
        DIN_, DH_, 0, 0, 0);

    // GEMM2 (transposed output): ET[b][h][n] = W2T[h,:]·H1[b][n,:] + b2[h]
    gemm_fp16<false, true><<<dim3(N_ / BN, DH_ / BM, B_), 256>>>(
        (const __half*)pW2T, (const __half*)pH1, b2, (__half*)pET,
        DH_, N_, 0, (size_t)N_ * DH_, (size_t)DH_ * N_);

    select_kernel<<<(B_ * DH_) / 8, 256>>>();
    decode1_kernel<<<dim3(8, 8), 128>>>(W3, b3);
    decode2_kernel<<<80, 256>>>(W4, b4, out);
}